// round 1
// baseline (speedup 1.0000x reference)
#include <cuda_runtime.h>
#include <cuda_bf16.h>
#include <cstdint>

// Problem constants
#define BATCH 2
#define LSEQ 1024
#define DMODEL 1024
#define DINNER 2048
#define DSTATE 16
#define DTRANK 64
#define DCONV 4
#define XDBL_W (DTRANK + 2*DSTATE)   // 96

// Scratch (device globals; no runtime allocation allowed)
__device__ float g_c1[BATCH * LSEQ * 2 * DINNER];   // x_and_res (B,L,4096)  32MB
__device__ float g_u[BATCH * LSEQ * DINNER];        // post conv+silu        16MB
__device__ float g_xdbl[BATCH * LSEQ * XDBL_W];     // dt|B|C                0.75MB
__device__ float g_delta[BATCH * LSEQ * DINNER];    // softplus delta        16MB
__device__ float g_yg[BATCH * LSEQ * DINNER];       // gated scan output     16MB

// ---------------------------------------------------------------------------
// Generic NT GEMM: C[m,n] = sum_k A[m*lda+k] * B[n*ldb+k]  (+ optional epilogue)
// 128x128 tile, BK=16, 256 threads, 8x8 per-thread micro-tile.
// EPI: 0 = none, 1 = bias[n] + softplus
// ---------------------------------------------------------------------------
#define BM 128
#define BN 128
#define BK 16
#define TM 8
#define TN 8

template<int EPI>
__global__ __launch_bounds__(256)
void gemm_nt_kernel(const float* __restrict__ A, int lda,
                    const float* __restrict__ B, int ldb,
                    float* __restrict__ C, int ldc,
                    int M, int N, int K,
                    const float* __restrict__ bias)
{
    __shared__ float As[BK][BM + 4];
    __shared__ float Bs[BK][BN + 4];

    const int tid = threadIdx.x;
    const int tx = tid & 15;          // N direction
    const int ty = tid >> 4;          // M direction
    const int m0 = blockIdx.y * BM;
    const int n0 = blockIdx.x * BN;

    float acc[TM][TN];
#pragma unroll
    for (int i = 0; i < TM; i++)
#pragma unroll
        for (int j = 0; j < TN; j++) acc[i][j] = 0.f;

    for (int k0 = 0; k0 < K; k0 += BK) {
        // ---- load A tile: 128 rows x 16 k = 512 float4 slots / 256 threads
#pragma unroll
        for (int i = 0; i < 2; i++) {
            int idx = tid + i * 256;
            int row = idx >> 2;
            int k4  = (idx & 3) << 2;
            int gm = m0 + row;
            float4 v = make_float4(0.f, 0.f, 0.f, 0.f);
            if (gm < M)
                v = *reinterpret_cast<const float4*>(A + (size_t)gm * lda + k0 + k4);
            As[k4 + 0][row] = v.x; As[k4 + 1][row] = v.y;
            As[k4 + 2][row] = v.z; As[k4 + 3][row] = v.w;
        }
        // ---- load B tile
#pragma unroll
        for (int i = 0; i < 2; i++) {
            int idx = tid + i * 256;
            int row = idx >> 2;
            int k4  = (idx & 3) << 2;
            int gn = n0 + row;
            float4 v = make_float4(0.f, 0.f, 0.f, 0.f);
            if (gn < N)
                v = *reinterpret_cast<const float4*>(B + (size_t)gn * ldb + k0 + k4);
            Bs[k4 + 0][row] = v.x; Bs[k4 + 1][row] = v.y;
            Bs[k4 + 2][row] = v.z; Bs[k4 + 3][row] = v.w;
        }
        __syncthreads();

#pragma unroll
        for (int k = 0; k < BK; k++) {
            float af[TM], bf[TN];
#pragma unroll
            for (int i = 0; i < TM; i++) af[i] = As[k][ty * TM + i];
#pragma unroll
            for (int j = 0; j < TN; j++) bf[j] = Bs[k][tx * TN + j];
#pragma unroll
            for (int i = 0; i < TM; i++)
#pragma unroll
                for (int j = 0; j < TN; j++)
                    acc[i][j] = fmaf(af[i], bf[j], acc[i][j]);
        }
        __syncthreads();
    }

    // ---- epilogue
#pragma unroll
    for (int i = 0; i < TM; i++) {
        int gm = m0 + ty * TM + i;
        if (gm >= M) continue;
#pragma unroll
        for (int j = 0; j < TN; j++) {
            int gn = n0 + tx * TN + j;
            if (gn >= N) continue;
            float v = acc[i][j];
            if (EPI == 1) {
                v += bias[gn];
                // softplus
                v = (v > 20.f) ? v : log1pf(__expf(v));
            }
            C[(size_t)gm * ldc + gn] = v;
        }
    }
}

// ---------------------------------------------------------------------------
// Depthwise causal conv (width 4) + bias + SiLU:  u = silu(conv(xz) + b_conv)
// xz = g_c1[..., 0:2048]
// ---------------------------------------------------------------------------
__global__ __launch_bounds__(256)
void conv_silu_kernel(const float* __restrict__ c1, const float* __restrict__ wc,
                      const float* __restrict__ bc, float* __restrict__ u)
{
    int idx = blockIdx.x * 256 + threadIdx.x;   // over B*L*DINNER = 2^22
    int d = idx & (DINNER - 1);
    int l = (idx >> 11) & (LSEQ - 1);
    int b = idx >> 21;

    const float* base = c1 + (size_t)b * LSEQ * (2 * DINNER) + d;
    float acc = bc[d];
    float w0 = wc[d * 4 + 0], w1 = wc[d * 4 + 1], w2 = wc[d * 4 + 2], w3 = wc[d * 4 + 3];
    if (l >= 3) acc = fmaf(w0, base[(size_t)(l - 3) * (2 * DINNER)], acc);
    if (l >= 2) acc = fmaf(w1, base[(size_t)(l - 2) * (2 * DINNER)], acc);
    if (l >= 1) acc = fmaf(w2, base[(size_t)(l - 1) * (2 * DINNER)], acc);
    acc = fmaf(w3, base[(size_t)l * (2 * DINNER)], acc);
    u[idx] = acc / (1.f + __expf(-acc));
}

// ---------------------------------------------------------------------------
// Selective scan. One thread per (b, d, n); 16-lane groups reduce over n.
// Fuses +u*D and *silu(res) gating.
// Block = 256 threads = 16 d's. Grid = (DINNER/16, BATCH).
// ---------------------------------------------------------------------------
__global__ __launch_bounds__(256)
void scan_kernel(const float* __restrict__ u, const float* __restrict__ delta,
                 const float* __restrict__ xdbl, const float* __restrict__ c1,
                 const float* __restrict__ A_log, const float* __restrict__ Dp,
                 float* __restrict__ yg)
{
    const int b = blockIdx.y;
    const int tid = threadIdx.x;
    const int n = tid & 15;
    const int dl = tid >> 4;
    const int d = blockIdx.x * 16 + dl;

    const float Av = -__expf(A_log[d * DSTATE + n]);
    const float Dv = Dp[d];
    float h = 0.f;

    const float* ud   = u     + (size_t)b * LSEQ * DINNER + d;
    const float* dd   = delta + (size_t)b * LSEQ * DINNER + d;
    const float* bptr = xdbl  + (size_t)b * LSEQ * XDBL_W + DTRANK + n;
    const float* cptr = bptr + DSTATE;
    const float* resp = c1 + (size_t)b * LSEQ * (2 * DINNER) + DINNER + d;
    float* yp = yg + (size_t)b * LSEQ * DINNER + d;

    for (int l = 0; l < LSEQ; l++) {
        float del = dd[(size_t)l * DINNER];
        float uv  = ud[(size_t)l * DINNER];
        float Bv  = bptr[(size_t)l * XDBL_W];
        float Cv  = cptr[(size_t)l * XDBL_W];

        h = fmaf(__expf(del * Av), h, (del * uv) * Bv);

        float p = h * Cv;
        p += __shfl_xor_sync(0xffffffffu, p, 8, 16);
        p += __shfl_xor_sync(0xffffffffu, p, 4, 16);
        p += __shfl_xor_sync(0xffffffffu, p, 2, 16);
        p += __shfl_xor_sync(0xffffffffu, p, 1, 16);

        if (n == 0) {
            float r = resp[(size_t)l * (2 * DINNER)];
            float y = fmaf(uv, Dv, p);
            float gate = r / (1.f + __expf(-r));
            yp[(size_t)l * DINNER] = y * gate;
        }
    }
}

// ---------------------------------------------------------------------------
// Launch
// ---------------------------------------------------------------------------
extern "C" void kernel_launch(void* const* d_in, const int* in_sizes, int n_in,
                              void* d_out, int out_size)
{
    const float* x       = (const float*)d_in[0];  // (B,L,1024)
    const float* W_in    = (const float*)d_in[1];  // (4096,1024)
    const float* W_conv  = (const float*)d_in[2];  // (2048,1,4)
    const float* b_conv  = (const float*)d_in[3];  // (2048)
    const float* W_xproj = (const float*)d_in[4];  // (96,2048)
    const float* W_dt    = (const float*)d_in[5];  // (2048,64)
    const float* b_dt    = (const float*)d_in[6];  // (2048)
    const float* A_log   = (const float*)d_in[7];  // (2048,16)
    const float* Dp      = (const float*)d_in[8];  // (2048)
    const float* W_out   = (const float*)d_in[9];  // (1024,2048)
    float* out = (float*)d_out;

    float *c1, *u, *xdbl, *delta, *yg;
    cudaGetSymbolAddress((void**)&c1,    g_c1);
    cudaGetSymbolAddress((void**)&u,     g_u);
    cudaGetSymbolAddress((void**)&xdbl,  g_xdbl);
    cudaGetSymbolAddress((void**)&delta, g_delta);
    cudaGetSymbolAddress((void**)&yg,    g_yg);

    const int M = BATCH * LSEQ;   // 2048 token rows

    // G1: x_and_res = X @ W_in^T   -> (2048, 4096)
    {
        dim3 grid((2 * DINNER + BN - 1) / BN, (M + BM - 1) / BM);
        gemm_nt_kernel<0><<<grid, 256>>>(x, DMODEL, W_in, DMODEL,
                                         c1, 2 * DINNER, M, 2 * DINNER, DMODEL, nullptr);
    }
    // conv + silu -> u (2048, 2048)
    {
        int total = BATCH * LSEQ * DINNER;
        conv_silu_kernel<<<total / 256, 256>>>(c1, W_conv, b_conv, u);
    }
    // G2: x_dbl = u @ W_xproj^T -> (2048, 96)
    {
        dim3 grid((XDBL_W + BN - 1) / BN, (M + BM - 1) / BM);
        gemm_nt_kernel<0><<<grid, 256>>>(u, DINNER, W_xproj, DINNER,
                                         xdbl, XDBL_W, M, XDBL_W, DINNER, nullptr);
    }
    // G3: delta = softplus(dt @ W_dt^T + b_dt) -> (2048, 2048)
    {
        dim3 grid((DINNER + BN - 1) / BN, (M + BM - 1) / BM);
        gemm_nt_kernel<1><<<grid, 256>>>(xdbl, XDBL_W, W_dt, DTRANK,
                                         delta, DINNER, M, DINNER, DTRANK, b_dt);
    }
    // selective scan (fused +u*D and gating) -> yg (2048, 2048)
    {
        dim3 grid(DINNER / 16, BATCH);
        scan_kernel<<<grid, 256>>>(u, delta, xdbl, c1, A_log, Dp, yg);
    }
    // G4: out = yg @ W_out^T -> (2048, 1024)
    {
        dim3 grid((DMODEL + BN - 1) / BN, (M + BM - 1) / BM);
        gemm_nt_kernel<0><<<grid, 256>>>(yg, DINNER, W_out, DINNER,
                                         out, DMODEL, M, DMODEL, DINNER, nullptr);
    }
}

// round 2
// speedup vs baseline: 1.6644x; 1.6644x over previous
#include <cuda_runtime.h>
#include <cuda_bf16.h>
#include <cstdint>

// Problem constants
#define BATCH 2
#define LSEQ 1024
#define DMODEL 1024
#define DINNER 2048
#define DSTATE 16
#define DTRANK 64
#define DCONV 4
#define XDBL_W (DTRANK + 2*DSTATE)   // 96

// Scratch (device globals; no runtime allocation allowed)
__device__ float g_c1[BATCH * LSEQ * 2 * DINNER];   // x_and_res (B,L,4096)
__device__ float g_u[BATCH * LSEQ * DINNER];        // post conv+silu
__device__ float g_xdbl[BATCH * LSEQ * XDBL_W];     // dt|B|C
__device__ float g_delta[BATCH * LSEQ * DINNER];    // softplus delta
__device__ float g_yg[BATCH * LSEQ * DINNER];       // gated scan output

// ---------------------------------------------------------------------------
// TF32 tensor-core NT GEMM: C[m,n] = sum_k A[m,k]*B[n,k]
// 128x128 tile, BK=16, 256 threads (8 warps as 4Mx2N), mma.m16n8k8 tf32,
// 2-stage cp.async pipeline. EPI: 1 = bias+softplus. ATOMIC: atomicAdd C.
// M must be a multiple of 128; K a multiple of 16 per split; N arbitrary.
// ---------------------------------------------------------------------------
#define BM 128
#define BN 128
#define BK 16
#define BKP 20   // padded K stride (floats): conflict-free fragment loads

__device__ __forceinline__ uint32_t f2tf32(float x) {
    uint32_t r;
    asm("cvt.rna.tf32.f32 %0, %1;\n" : "=r"(r) : "f"(x));
    return r;
}

__device__ __forceinline__ void mma_tf32(float* d, const uint32_t* a, const uint32_t* b) {
    asm volatile(
        "mma.sync.aligned.m16n8k8.row.col.f32.tf32.tf32.f32 "
        "{%0,%1,%2,%3}, {%4,%5,%6,%7}, {%8,%9}, {%0,%1,%2,%3};\n"
        : "+f"(d[0]), "+f"(d[1]), "+f"(d[2]), "+f"(d[3])
        : "r"(a[0]), "r"(a[1]), "r"(a[2]), "r"(a[3]), "r"(b[0]), "r"(b[1]));
}

__device__ __forceinline__ void ldgsts16(uint32_t s, const float* g) {
    asm volatile("cp.async.ca.shared.global [%0], [%1], 16;\n" :: "r"(s), "l"(g));
}
__device__ __forceinline__ void ldgsts16_guard(uint32_t s, const float* g, bool ok) {
    int sz = ok ? 16 : 0;
    asm volatile("cp.async.ca.shared.global [%0], [%1], 16, %2;\n" :: "r"(s), "l"(g), "r"(sz));
}
__device__ __forceinline__ void cp_commit() {
    asm volatile("cp.async.commit_group;\n" ::: "memory");
}
template<int NW> __device__ __forceinline__ void cp_wait() {
    asm volatile("cp.async.wait_group %0;\n" :: "n"(NW) : "memory");
}

__device__ __forceinline__ float softplus_f(float v) {
    return (v > 20.f) ? v : log1pf(__expf(v));
}

template<int EPI, int ATOMIC>
__global__ __launch_bounds__(256)
void gemm_tc(const float* __restrict__ A, int lda,
             const float* __restrict__ B, int ldb,
             float* __restrict__ C, int ldc,
             int M, int N, int K,
             const float* __restrict__ bias)
{
    __shared__ float As[2][BM][BKP];
    __shared__ float Bs[2][BN][BKP];

    const int tid  = threadIdx.x;
    const int lane = tid & 31;
    const int warp = tid >> 5;
    const int wM = warp >> 1;        // 0..3
    const int wN = warp & 1;         // 0..1
    const int g = lane >> 2;         // 0..7 (groupID)
    const int t = lane & 3;          // 0..3 (threadID_in_group)

    const int m0 = blockIdx.y * BM;
    const int n0 = blockIdx.x * BN;

    const int Kz   = K / gridDim.z;
    const int kbeg = blockIdx.z * Kz;
    const int nk   = Kz / BK;

    // tile loader
    auto load_tiles = [&](int st, int kk0) {
        uint32_t sA = (uint32_t)__cvta_generic_to_shared(&As[st][0][0]);
        uint32_t sB = (uint32_t)__cvta_generic_to_shared(&Bs[st][0][0]);
#pragma unroll
        for (int i = 0; i < 2; i++) {
            int idx = tid + i * 256;
            int row = idx >> 2;
            int k4  = (idx & 3) << 2;
            // A (always in bounds: M multiple of 128, K multiple of 16)
            ldgsts16(sA + (row * BKP + k4) * 4,
                     A + (size_t)(m0 + row) * lda + kk0 + k4);
            // B (guard N)
            int gn = n0 + row;
            bool ok = gn < N;
            const float* gp = B + (size_t)(ok ? gn : 0) * ldb + kk0 + k4;
            ldgsts16_guard(sB + (row * BKP + k4) * 4, gp, ok);
        }
    };

    float acc[2][8][4];
#pragma unroll
    for (int mt = 0; mt < 2; mt++)
#pragma unroll
        for (int nt = 0; nt < 8; nt++)
#pragma unroll
            for (int i = 0; i < 4; i++) acc[mt][nt][i] = 0.f;

    load_tiles(0, kbeg);
    cp_commit();

    for (int it = 0; it < nk; ++it) {
        const int st = it & 1;
        if (it + 1 < nk) {
            load_tiles((it + 1) & 1, kbeg + (it + 1) * BK);
            cp_commit();
            cp_wait<1>();
        } else {
            cp_wait<0>();
        }
        __syncthreads();

#pragma unroll
        for (int ks = 0; ks < BK; ks += 8) {
            uint32_t a[2][4], b[8][2];
#pragma unroll
            for (int mt = 0; mt < 2; mt++) {
                int r = wM * 32 + mt * 16 + g;
                a[mt][0] = f2tf32(As[st][r][ks + t]);
                a[mt][1] = f2tf32(As[st][r + 8][ks + t]);
                a[mt][2] = f2tf32(As[st][r][ks + t + 4]);
                a[mt][3] = f2tf32(As[st][r + 8][ks + t + 4]);
            }
#pragma unroll
            for (int nt = 0; nt < 8; nt++) {
                int n = wN * 64 + nt * 8 + g;
                b[nt][0] = f2tf32(Bs[st][n][ks + t]);
                b[nt][1] = f2tf32(Bs[st][n][ks + t + 4]);
            }
#pragma unroll
            for (int mt = 0; mt < 2; mt++)
#pragma unroll
                for (int nt = 0; nt < 8; nt++)
                    mma_tf32(acc[mt][nt], a[mt], b[nt]);
        }
        __syncthreads();
    }

    // epilogue
#pragma unroll
    for (int mt = 0; mt < 2; mt++) {
        int r0 = m0 + wM * 32 + mt * 16 + g;
#pragma unroll
        for (int nt = 0; nt < 8; nt++) {
            int c = n0 + wN * 64 + nt * 8 + 2 * t;
            if (c >= N) continue;
            float v0 = acc[mt][nt][0], v1 = acc[mt][nt][1];
            float v2 = acc[mt][nt][2], v3 = acc[mt][nt][3];
            if (EPI == 1) {
                float b0 = bias[c], b1 = bias[c + 1];
                v0 = softplus_f(v0 + b0); v1 = softplus_f(v1 + b1);
                v2 = softplus_f(v2 + b0); v3 = softplus_f(v3 + b1);
            }
            if (ATOMIC) {
                atomicAdd(&C[(size_t)r0 * ldc + c],           v0);
                atomicAdd(&C[(size_t)r0 * ldc + c + 1],       v1);
                atomicAdd(&C[(size_t)(r0 + 8) * ldc + c],     v2);
                atomicAdd(&C[(size_t)(r0 + 8) * ldc + c + 1], v3);
            } else {
                C[(size_t)r0 * ldc + c]           = v0;
                C[(size_t)r0 * ldc + c + 1]       = v1;
                C[(size_t)(r0 + 8) * ldc + c]     = v2;
                C[(size_t)(r0 + 8) * ldc + c + 1] = v3;
            }
        }
    }
}

// ---------------------------------------------------------------------------
// Depthwise causal conv (width 4) + bias + SiLU
// ---------------------------------------------------------------------------
__global__ __launch_bounds__(256)
void conv_silu_kernel(const float* __restrict__ c1, const float* __restrict__ wc,
                      const float* __restrict__ bc, float* __restrict__ u)
{
    int idx = blockIdx.x * 256 + threadIdx.x;
    int d = idx & (DINNER - 1);
    int l = (idx >> 11) & (LSEQ - 1);
    int b = idx >> 21;

    const float* base = c1 + (size_t)b * LSEQ * (2 * DINNER) + d;
    float acc = bc[d];
    float w0 = wc[d * 4 + 0], w1 = wc[d * 4 + 1], w2 = wc[d * 4 + 2], w3 = wc[d * 4 + 3];
    if (l >= 3) acc = fmaf(w0, base[(size_t)(l - 3) * (2 * DINNER)], acc);
    if (l >= 2) acc = fmaf(w1, base[(size_t)(l - 2) * (2 * DINNER)], acc);
    if (l >= 1) acc = fmaf(w2, base[(size_t)(l - 1) * (2 * DINNER)], acc);
    acc = fmaf(w3, base[(size_t)l * (2 * DINNER)], acc);
    u[idx] = acc / (1.f + __expf(-acc));
}

// ---------------------------------------------------------------------------
// Selective scan. Thread per (b,d,n); 16-lane reduce over n; fused gating.
// ---------------------------------------------------------------------------
__global__ __launch_bounds__(256)
void scan_kernel(const float* __restrict__ u, const float* __restrict__ delta,
                 const float* __restrict__ xdbl, const float* __restrict__ c1,
                 const float* __restrict__ A_log, const float* __restrict__ Dp,
                 float* __restrict__ yg)
{
    const int b = blockIdx.y;
    const int tid = threadIdx.x;
    const int n = tid & 15;
    const int dl = tid >> 4;
    const int d = blockIdx.x * 16 + dl;

    const float Av = -__expf(A_log[d * DSTATE + n]);
    const float Dv = Dp[d];
    float h = 0.f;

    const float* ud   = u     + (size_t)b * LSEQ * DINNER + d;
    const float* dd   = delta + (size_t)b * LSEQ * DINNER + d;
    const float* bptr = xdbl  + (size_t)b * LSEQ * XDBL_W + DTRANK + n;
    const float* cptr = bptr + DSTATE;
    const float* resp = c1 + (size_t)b * LSEQ * (2 * DINNER) + DINNER + d;
    float* yp = yg + (size_t)b * LSEQ * DINNER + d;

    for (int l = 0; l < LSEQ; l++) {
        float del = dd[(size_t)l * DINNER];
        float uv  = ud[(size_t)l * DINNER];
        float Bv  = bptr[(size_t)l * XDBL_W];
        float Cv  = cptr[(size_t)l * XDBL_W];

        h = fmaf(__expf(del * Av), h, (del * uv) * Bv);

        float p = h * Cv;
        p += __shfl_xor_sync(0xffffffffu, p, 8, 16);
        p += __shfl_xor_sync(0xffffffffu, p, 4, 16);
        p += __shfl_xor_sync(0xffffffffu, p, 2, 16);
        p += __shfl_xor_sync(0xffffffffu, p, 1, 16);

        if (n == 0) {
            float r = resp[(size_t)l * (2 * DINNER)];
            float y = fmaf(uv, Dv, p);
            float gate = r / (1.f + __expf(-r));
            yp[(size_t)l * DINNER] = y * gate;
        }
    }
}

// ---------------------------------------------------------------------------
// Launch
// ---------------------------------------------------------------------------
extern "C" void kernel_launch(void* const* d_in, const int* in_sizes, int n_in,
                              void* d_out, int out_size)
{
    const float* x       = (const float*)d_in[0];
    const float* W_in    = (const float*)d_in[1];
    const float* W_conv  = (const float*)d_in[2];
    const float* b_conv  = (const float*)d_in[3];
    const float* W_xproj = (const float*)d_in[4];
    const float* W_dt    = (const float*)d_in[5];
    const float* b_dt    = (const float*)d_in[6];
    const float* A_log   = (const float*)d_in[7];
    const float* Dp      = (const float*)d_in[8];
    const float* W_out   = (const float*)d_in[9];
    float* out = (float*)d_out;

    float *c1, *u, *xdbl, *delta, *yg;
    cudaGetSymbolAddress((void**)&c1,    g_c1);
    cudaGetSymbolAddress((void**)&u,     g_u);
    cudaGetSymbolAddress((void**)&xdbl,  g_xdbl);
    cudaGetSymbolAddress((void**)&delta, g_delta);
    cudaGetSymbolAddress((void**)&yg,    g_yg);

    const int M = BATCH * LSEQ;   // 2048

    // G1: x_and_res = X @ W_in^T -> (2048, 4096)
    {
        dim3 grid((2 * DINNER) / BN, M / BM, 1);
        gemm_tc<0, 0><<<grid, 256>>>(x, DMODEL, W_in, DMODEL,
                                     c1, 2 * DINNER, M, 2 * DINNER, DMODEL, nullptr);
    }
    // conv + silu -> u
    {
        int total = BATCH * LSEQ * DINNER;
        conv_silu_kernel<<<total / 256, 256>>>(c1, W_conv, b_conv, u);
    }
    // G2: x_dbl = u @ W_xproj^T -> (2048, 96), split-K=8 + atomics
    {
        cudaMemsetAsync(xdbl, 0, (size_t)BATCH * LSEQ * XDBL_W * sizeof(float), 0);
        dim3 grid(1, M / BM, 8);
        gemm_tc<0, 1><<<grid, 256>>>(u, DINNER, W_xproj, DINNER,
                                     xdbl, XDBL_W, M, XDBL_W, DINNER, nullptr);
    }
    // G3: delta = softplus(dt @ W_dt^T + b_dt) -> (2048, 2048)
    {
        dim3 grid(DINNER / BN, M / BM, 1);
        gemm_tc<1, 0><<<grid, 256>>>(xdbl, XDBL_W, W_dt, DTRANK,
                                     delta, DINNER, M, DINNER, DTRANK, b_dt);
    }
    // scan -> yg
    {
        dim3 grid(DINNER / 16, BATCH);
        scan_kernel<<<grid, 256>>>(u, delta, xdbl, c1, A_log, Dp, yg);
    }
    // G4: out = yg @ W_out^T -> (2048, 1024)
    {
        dim3 grid(DMODEL / BN, M / BM, 1);
        gemm_tc<0, 0><<<grid, 256>>>(yg, DINNER, W_out, DINNER,
                                     out, DMODEL, M, DMODEL, DINNER, nullptr);
    }
}